// round 8
// baseline (speedup 1.0000x reference)
#include <cuda_runtime.h>
#include <cuda_bf16.h>

#define NRELS 20

struct EdgeIn {
    float p0, p1, p2, c0, c1, c2;
    float ep[9];
    float b;
    int r;
};

struct EdgeOut {
    float cm, cp0, cp1, cp2, am, a0, a1, a2;
};

__device__ __forceinline__ void load_edge(
    const float* __restrict__ prnt, const float* __restrict__ child,
    const float* __restrict__ eps,  const float* __restrict__ beta,
    const int* __restrict__ rels, int i, EdgeIn& E)
{
    E.r  = __ldcs(&rels[i]);
    E.b  = __ldcs(&beta[i]);
    E.p0 = __ldcs(&prnt[3 * (size_t)i + 0]);
    E.p1 = __ldcs(&prnt[3 * (size_t)i + 1]);
    E.p2 = __ldcs(&prnt[3 * (size_t)i + 2]);
    E.c0 = __ldcs(&child[3 * (size_t)i + 0]);
    E.c1 = __ldcs(&child[3 * (size_t)i + 1]);
    E.c2 = __ldcs(&child[3 * (size_t)i + 2]);
    const float* epp = eps + 9 * (size_t)i;
    #pragma unroll
    for (int k = 0; k < 9; k++) E.ep[k] = __ldcs(&epp[k]);
}

__device__ __forceinline__ void compute_edge(
    const EdgeIn& E, const float* __restrict__ s_mu,
    const float* __restrict__ s_sig, EdgeOut& O)
{
    const float* mu = &s_mu[9 * E.r];
    const float* sg = &s_sig[9 * E.r];

    float l0 = fmaf(fmaf(sg[0], E.ep[0], mu[0]), E.c0,
               fmaf(fmaf(sg[1], E.ep[1], mu[1]), E.c1,
                    fmaf(sg[2], E.ep[2], mu[2]) * E.c2));
    float l1 = fmaf(fmaf(sg[3], E.ep[3], mu[3]), E.c0,
               fmaf(fmaf(sg[4], E.ep[4], mu[4]), E.c1,
                    fmaf(sg[5], E.ep[5], mu[5]) * E.c2));
    float l2 = fmaf(fmaf(sg[6], E.ep[6], mu[6]), E.c0,
               fmaf(fmaf(sg[7], E.ep[7], mu[7]), E.c1,
                    fmaf(sg[8], E.ep[8], mu[8]) * E.c2));

    float m  = fmaxf(l0, fmaxf(l1, l2));
    float e0 = __expf(l0 - m);
    float e1 = __expf(l1 - m);
    float e2 = __expf(l2 - m);
    float inv_es = __frcp_rn(e0 + e1 + e2);
    float cp0 = e0 * inv_es;
    float cp1 = e1 * inv_es;
    float cp2 = e2 * inv_es;

    float child_sum = E.c0 + E.c1 + E.c2;
    float prnt_sum  = E.p0 + E.p1 + E.p2;
    bool child_mask = (child_sum != 0.0f);
    bool copy_mask  = child_mask && (prnt_sum == 0.0f);
    bool alpha_mask = child_mask && (prnt_sum != 0.0f);

    float z0 = fmaxf(0.01f, E.p0 + cp0);
    float z1 = fmaxf(0.01f, E.p1 + cp1);
    float z2 = fmaxf(0.01f, E.p2 + cp2);
    float inv_zs = __frcp_rn(z0 + z1 + z2);
    z0 *= inv_zs; z1 *= inv_zs; z2 *= inv_zs;
    float entropy = -(z0 * __logf(z0) + z1 * __logf(z1) + z2 * __logf(z2));

    float dot  = E.p0 * cp0 + E.p1 * cp1 + E.p2 * cp2;
    float sqp  = E.p0 * E.p0 + E.p1 * E.p1 + E.p2 * E.p2;
    float sqc  = cp0 * cp0 + cp1 * cp1 + cp2 * cp2;
    float np   = (sqp == 0.0f) ? 0.0f : __fsqrt_rn(sqp);
    float nc   = (sqc == 0.0f) ? 0.0f : __fsqrt_rn(sqc);
    float norm = np * nc;
    norm = (norm == 0.0f) ? 1.0f : norm;
    float cosv = fmaxf(0.01f, dot * __frcp_rn(norm));
    float s = 42.0f * cosv * __frcp_rn(entropy);

    float ob = 1.0f - E.b;
    float a0 = fmaf(ob, E.p0, E.b * cp0) * s;
    float a1 = fmaf(ob, E.p1, E.b * cp1) * s;
    float a2 = fmaf(ob, E.p2, E.b * cp2) * s;

    O.cm  = copy_mask ? 1.0f : 0.0f;
    O.cp0 = copy_mask ? cp0 : 0.0f;
    O.cp1 = copy_mask ? cp1 : 0.0f;
    O.cp2 = copy_mask ? cp2 : 0.0f;
    O.am  = alpha_mask ? 1.0f : 0.0f;
    O.a0  = alpha_mask ? a0 : 0.0f;
    O.a1  = alpha_mask ? a1 : 0.0f;
    O.a2  = alpha_mask ? a2 : 0.0f;
}

__device__ __forceinline__ void store_edge(float* __restrict__ out, size_t N,
                                           int i, const EdgeOut& O)
{
    __stcs(&out[i], O.cm);
    float* ocp = out + N + 3 * (size_t)i;
    __stcs(&ocp[0], O.cp0);
    __stcs(&ocp[1], O.cp1);
    __stcs(&ocp[2], O.cp2);
    __stcs(&out[4 * N + i], O.am);
    float* oal = out + 5 * N + 3 * (size_t)i;
    __stcs(&oal[0], O.a0);
    __stcs(&oal[1], O.a1);
    __stcs(&oal[2], O.a2);
}

// Persistent grid-stride kernel; 2 interleaved edges per iteration for MLP.
__global__ __launch_bounds__(256)
void alpha_model_persist(const float* __restrict__ prnt,
                         const float* __restrict__ child,
                         const float* __restrict__ rel_mu,
                         const float* __restrict__ rel_sigma,
                         const float* __restrict__ eps,
                         const float* __restrict__ beta,
                         const int*   __restrict__ rels,
                         float* __restrict__ out,
                         int n)
{
    __shared__ float s_mu[NRELS * 9];
    __shared__ float s_sig[NRELS * 9];
    for (int t = threadIdx.x; t < NRELS * 9; t += blockDim.x) {
        s_mu[t]  = rel_mu[t];
        s_sig[t] = rel_sigma[t];
    }
    __syncthreads();

    size_t N = n;
    int stride = gridDim.x * blockDim.x;
    int i0 = blockIdx.x * blockDim.x + threadIdx.x;

    for (int i = i0; i < n; i += 2 * stride) {
        int j = i + stride;
        bool hasj = (j < n);

        // ---- issue both iterations' loads back-to-back (deep MLP) ----
        EdgeIn Ei, Ej;
        load_edge(prnt, child, eps, beta, rels, i, Ei);
        if (hasj) load_edge(prnt, child, eps, beta, rels, j, Ej);

        EdgeOut Oi;
        compute_edge(Ei, s_mu, s_sig, Oi);
        store_edge(out, N, i, Oi);

        if (hasj) {
            EdgeOut Oj;
            compute_edge(Ej, s_mu, s_sig, Oj);
            store_edge(out, N, j, Oj);
        }
    }
}

extern "C" void kernel_launch(void* const* d_in, const int* in_sizes, int n_in,
                              void* d_out, int out_size) {
    const float* prnt   = (const float*)d_in[0];
    const float* child  = (const float*)d_in[1];
    const float* rel_mu = (const float*)d_in[2];
    const float* rel_sg = (const float*)d_in[3];
    const float* eps    = (const float*)d_in[4];
    const float* beta   = (const float*)d_in[5];
    const int*   rels   = (const int*)d_in[6];
    float* out = (float*)d_out;

    int n = in_sizes[5];  // beta element count == N

    // Persistent launch: 8 CTAs/SM * 148 SMs (grid-stride covers any n)
    int blocks = 148 * 8;
    int threads = 256;
    int max_blocks = (n + threads - 1) / threads;
    if (blocks > max_blocks) blocks = max_blocks;

    alpha_model_persist<<<blocks, threads>>>(prnt, child, rel_mu, rel_sg,
                                             eps, beta, rels, out, n);
}

// round 9
// speedup vs baseline: 1.0639x; 1.0639x over previous
#include <cuda_runtime.h>
#include <cuda_bf16.h>
#include <cstdint>

#define NRELS 20
#define EPB 256                      // edges per tile == threads per block
#define TILE_BYTES 17408             // 3072+3072+9216+1024+1024

// smem tile layout (bytes): prnt[0,3072) child[3072,6144) eps[6144,15360)
//                           beta[15360,16384) rels[16384,17408)
#define OFF_P 0
#define OFF_C 3072
#define OFF_E 6144
#define OFF_B 15360
#define OFF_R 16384

__device__ __forceinline__ uint32_t smem_u32(const void* p) {
    uint32_t a;
    asm("{ .reg .u64 t; cvta.to.shared.u64 t, %1; cvt.u32.u64 %0, t; }"
        : "=r"(a) : "l"(p));
    return a;
}

__device__ __forceinline__ void mbar_init(uint32_t mbar, uint32_t cnt) {
    asm volatile("mbarrier.init.shared.b64 [%0], %1;" :: "r"(mbar), "r"(cnt) : "memory");
}
__device__ __forceinline__ void mbar_expect_tx(uint32_t mbar, uint32_t bytes) {
    asm volatile("mbarrier.arrive.expect_tx.shared.b64 _, [%0], %1;"
                 :: "r"(mbar), "r"(bytes) : "memory");
}
__device__ __forceinline__ void mbar_wait(uint32_t mbar, uint32_t phase) {
    uint32_t done;
    asm volatile(
        "{\n\t.reg .pred p;\n\t"
        "mbarrier.try_wait.parity.acquire.cta.shared::cta.b64 p, [%1], %2;\n\t"
        "selp.b32 %0, 1, 0, p;\n\t}"
        : "=r"(done) : "r"(mbar), "r"(phase) : "memory");
    if (!done) {
        asm volatile(
            "{\n\t.reg .pred P1;\n\t"
            "WL_%=:\n\t"
            "mbarrier.try_wait.parity.acquire.cta.shared::cta.b64 P1, [%0], %1, 0x989680;\n\t"
            "@P1 bra.uni WD_%=;\n\t"
            "bra.uni WL_%=;\n\t"
            "WD_%=:\n\t}"
            :: "r"(mbar), "r"(phase) : "memory");
    }
}
__device__ __forceinline__ void bulk_cp(uint32_t dst_smem, const void* src_gmem,
                                        uint32_t bytes, uint32_t mbar) {
    asm volatile(
        "cp.async.bulk.shared::cta.global.mbarrier::complete_tx::bytes "
        "[%0], [%1], %2, [%3];"
        :: "r"(dst_smem), "l"(src_gmem), "r"(bytes), "r"(mbar) : "memory");
}

// ---------------------------------------------------------------------------
__device__ __forceinline__ void edge_compute(
    float p0, float p1, float p2,
    float c0, float c1, float c2,
    const float* __restrict__ mu, const float* __restrict__ sg,
    const float* ep, float b,
    float& cm, float& ocp0, float& ocp1, float& ocp2,
    float& am, float& oal0, float& oal1, float& oal2)
{
    float l0 = fmaf(fmaf(sg[0], ep[0], mu[0]), c0,
               fmaf(fmaf(sg[1], ep[1], mu[1]), c1,
                    fmaf(sg[2], ep[2], mu[2]) * c2));
    float l1 = fmaf(fmaf(sg[3], ep[3], mu[3]), c0,
               fmaf(fmaf(sg[4], ep[4], mu[4]), c1,
                    fmaf(sg[5], ep[5], mu[5]) * c2));
    float l2 = fmaf(fmaf(sg[6], ep[6], mu[6]), c0,
               fmaf(fmaf(sg[7], ep[7], mu[7]), c1,
                    fmaf(sg[8], ep[8], mu[8]) * c2));

    float m  = fmaxf(l0, fmaxf(l1, l2));
    float e0 = __expf(l0 - m);
    float e1 = __expf(l1 - m);
    float e2 = __expf(l2 - m);
    float inv_es = __frcp_rn(e0 + e1 + e2);
    float cp0 = e0 * inv_es, cp1 = e1 * inv_es, cp2 = e2 * inv_es;

    float child_sum = c0 + c1 + c2;
    float prnt_sum  = p0 + p1 + p2;
    bool child_mask = (child_sum != 0.0f);
    bool copy_mask  = child_mask && (prnt_sum == 0.0f);
    bool alpha_mask = child_mask && (prnt_sum != 0.0f);

    float z0 = fmaxf(0.01f, p0 + cp0);
    float z1 = fmaxf(0.01f, p1 + cp1);
    float z2 = fmaxf(0.01f, p2 + cp2);
    float inv_zs = __frcp_rn(z0 + z1 + z2);
    z0 *= inv_zs; z1 *= inv_zs; z2 *= inv_zs;
    float entropy = -(z0 * __logf(z0) + z1 * __logf(z1) + z2 * __logf(z2));

    float dot  = p0 * cp0 + p1 * cp1 + p2 * cp2;
    float sqp  = p0 * p0 + p1 * p1 + p2 * p2;
    float sqc  = cp0 * cp0 + cp1 * cp1 + cp2 * cp2;
    float np   = (sqp == 0.0f) ? 0.0f : __fsqrt_rn(sqp);
    float nc   = (sqc == 0.0f) ? 0.0f : __fsqrt_rn(sqc);
    float norm = np * nc;
    norm = (norm == 0.0f) ? 1.0f : norm;
    float cosv = fmaxf(0.01f, dot * __frcp_rn(norm));
    float s = 42.0f * cosv * __frcp_rn(entropy);

    float ob = 1.0f - b;
    float a0 = fmaf(ob, p0, b * cp0) * s;
    float a1 = fmaf(ob, p1, b * cp1) * s;
    float a2 = fmaf(ob, p2, b * cp2) * s;

    cm   = copy_mask ? 1.0f : 0.0f;
    ocp0 = copy_mask ? cp0 : 0.0f;
    ocp1 = copy_mask ? cp1 : 0.0f;
    ocp2 = copy_mask ? cp2 : 0.0f;
    am   = alpha_mask ? 1.0f : 0.0f;
    oal0 = alpha_mask ? a0 : 0.0f;
    oal1 = alpha_mask ? a1 : 0.0f;
    oal2 = alpha_mask ? a2 : 0.0f;
}

// ---------------------------------------------------------------------------
// Persistent CTAs, double-buffered cp.async.bulk tile prefetch into smem.
// ---------------------------------------------------------------------------
__global__ __launch_bounds__(EPB)
void alpha_model_bulk(const float* __restrict__ prnt,
                      const float* __restrict__ child,
                      const float* __restrict__ rel_mu,
                      const float* __restrict__ rel_sigma,
                      const float* __restrict__ eps,
                      const float* __restrict__ beta,
                      const int*   __restrict__ rels,
                      float* __restrict__ out,
                      int n)
{
    __shared__ __align__(128) unsigned char sbuf[2][TILE_BYTES];
    __shared__ float s_mu[NRELS * 9];
    __shared__ float s_sig[NRELS * 9];
    __shared__ __align__(8) unsigned long long mbar_storage[2];

    int tid = threadIdx.x;
    for (int t = tid; t < NRELS * 9; t += EPB) {
        s_mu[t]  = rel_mu[t];
        s_sig[t] = rel_sigma[t];
    }
    uint32_t mb0 = smem_u32(&mbar_storage[0]);
    uint32_t mb1 = smem_u32(&mbar_storage[1]);
    if (tid == 0) { mbar_init(mb0, 1); mbar_init(mb1, 1); }
    __syncthreads();

    const uint32_t mb[2]  = { mb0, mb1 };
    const uint32_t sb[2]  = { smem_u32(sbuf[0]), smem_u32(sbuf[1]) };

    int ntiles = n / EPB;            // full tiles
    int G = gridDim.x;
    size_t N = n;

    // helper lambda-ish: issue tile t into buffer b (tid 0 only)
    auto issue = [&](int t, int b) {
        mbar_expect_tx(mb[b], TILE_BYTES);
        bulk_cp(sb[b] + OFF_P, prnt  + 3 * (size_t)t * EPB, 3 * EPB * 4, mb[b]);
        bulk_cp(sb[b] + OFF_C, child + 3 * (size_t)t * EPB, 3 * EPB * 4, mb[b]);
        bulk_cp(sb[b] + OFF_E, eps   + 9 * (size_t)t * EPB, 9 * EPB * 4, mb[b]);
        bulk_cp(sb[b] + OFF_B, beta  + (size_t)t * EPB,     EPB * 4,     mb[b]);
        bulk_cp(sb[b] + OFF_R, rels  + (size_t)t * EPB,     EPB * 4,     mb[b]);
    };

    int t0 = blockIdx.x;
    if (t0 < ntiles && tid == 0) issue(t0, 0);

    int ph[2] = { 0, 0 };
    int k = 0;
    for (int t = t0; t < ntiles; t += G, k++) {
        int b = k & 1;
        int tn = t + G;
        if (tn < ntiles && tid == 0) issue(tn, b ^ 1);   // buffer b^1 free: synced last iter

        mbar_wait(mb[b], ph[b]);
        ph[b] ^= 1;

        const float* sp = (const float*)(sbuf[b] + OFF_P);
        const float* sc = (const float*)(sbuf[b] + OFF_C);
        const float* se = (const float*)(sbuf[b] + OFF_E);
        const float* sbta = (const float*)(sbuf[b] + OFF_B);
        const int*   srl = (const int*)(sbuf[b] + OFF_R);

        int i = t * EPB + tid;

        float p0 = sp[3 * tid], p1 = sp[3 * tid + 1], p2 = sp[3 * tid + 2];
        float c0 = sc[3 * tid], c1 = sc[3 * tid + 1], c2 = sc[3 * tid + 2];
        float ep[9];
        #pragma unroll
        for (int q = 0; q < 9; q++) ep[q] = se[9 * tid + q];
        float bb = sbta[tid];
        int   r  = srl[tid];

        float cm, ocp0, ocp1, ocp2, am, oal0, oal1, oal2;
        edge_compute(p0, p1, p2, c0, c1, c2,
                     &s_mu[9 * r], &s_sig[9 * r], ep, bb,
                     cm, ocp0, ocp1, ocp2, am, oal0, oal1, oal2);

        __stcs(&out[i], cm);
        float* ocp = out + N + 3 * (size_t)i;
        __stcs(&ocp[0], ocp0);
        __stcs(&ocp[1], ocp1);
        __stcs(&ocp[2], ocp2);
        __stcs(&out[4 * N + i], am);
        float* oal = out + 5 * N + 3 * (size_t)i;
        __stcs(&oal[0], oal0);
        __stcs(&oal[1], oal1);
        __stcs(&oal[2], oal2);

        __syncthreads();   // all threads done with buffer b before its reuse
    }

    // ---- tail (n not multiple of EPB): direct scalar path ----
    int tail_start = ntiles * EPB;
    for (int i = tail_start + blockIdx.x * EPB + tid; i < n; i += G * EPB) {
        int r = rels[i];
        float bb = beta[i];
        float p0 = prnt[3 * (size_t)i], p1 = prnt[3 * (size_t)i + 1], p2 = prnt[3 * (size_t)i + 2];
        float c0 = child[3 * (size_t)i], c1 = child[3 * (size_t)i + 1], c2 = child[3 * (size_t)i + 2];
        float ep[9];
        #pragma unroll
        for (int q = 0; q < 9; q++) ep[q] = eps[9 * (size_t)i + q];

        float cm, ocp0, ocp1, ocp2, am, oal0, oal1, oal2;
        edge_compute(p0, p1, p2, c0, c1, c2,
                     &s_mu[9 * r], &s_sig[9 * r], ep, bb,
                     cm, ocp0, ocp1, ocp2, am, oal0, oal1, oal2);

        out[i] = cm;
        out[N + 3 * (size_t)i + 0] = ocp0;
        out[N + 3 * (size_t)i + 1] = ocp1;
        out[N + 3 * (size_t)i + 2] = ocp2;
        out[4 * N + i] = am;
        out[5 * N + 3 * (size_t)i + 0] = oal0;
        out[5 * N + 3 * (size_t)i + 1] = oal1;
        out[5 * N + 3 * (size_t)i + 2] = oal2;
    }
}

extern "C" void kernel_launch(void* const* d_in, const int* in_sizes, int n_in,
                              void* d_out, int out_size) {
    const float* prnt   = (const float*)d_in[0];
    const float* child  = (const float*)d_in[1];
    const float* rel_mu = (const float*)d_in[2];
    const float* rel_sg = (const float*)d_in[3];
    const float* eps    = (const float*)d_in[4];
    const float* beta   = (const float*)d_in[5];
    const int*   rels   = (const int*)d_in[6];
    float* out = (float*)d_out;

    int n = in_sizes[5];  // beta element count == N

    int ntiles = n / EPB;
    int blocks = 148 * 6;                 // ~6 CTAs/SM (smem-bound)
    if (ntiles > 0 && blocks > ntiles) blocks = ntiles;
    if (ntiles == 0) blocks = 1;          // tail-only

    alpha_model_bulk<<<blocks, EPB>>>(prnt, child, rel_mu, rel_sg,
                                      eps, beta, rels, out, n);
}

// round 10
// speedup vs baseline: 1.1044x; 1.0381x over previous
#include <cuda_runtime.h>
#include <cuda_bf16.h>

#define NRELS 20

// Loads with 256B L2 prefetch hint — doubles L2 fill granularity on these
// perfectly-sequential one-touch streams (every prefetched byte is consumed).
__device__ __forceinline__ float ld_pf(const float* p) {
    float v;
    asm("ld.global.L2::256B.f32 %0, [%1];" : "=f"(v) : "l"(p));
    return v;
}
__device__ __forceinline__ int ld_pf_i(const int* p) {
    int v;
    asm("ld.global.L2::256B.b32 %0, [%1];" : "=r"(v) : "l"(p));
    return v;
}

__global__ __launch_bounds__(256, 8)
void alpha_model_pf(const float* __restrict__ prnt,
                    const float* __restrict__ child,
                    const float* __restrict__ rel_mu,
                    const float* __restrict__ rel_sigma,
                    const float* __restrict__ eps,
                    const float* __restrict__ beta,
                    const int*   __restrict__ rels,
                    float* __restrict__ out,
                    int n)
{
    __shared__ float s_mu[NRELS * 9];
    __shared__ float s_sig[NRELS * 9];
    for (int t = threadIdx.x; t < NRELS * 9; t += blockDim.x) {
        s_mu[t]  = rel_mu[t];
        s_sig[t] = rel_sigma[t];
    }
    __syncthreads();

    int i = blockIdx.x * blockDim.x + threadIdx.x;
    if (i >= n) return;

    // ---- loads (prefetch-hinted, coalesced) ----
    int   r = ld_pf_i(&rels[i]);
    float b = ld_pf(&beta[i]);

    float p0 = ld_pf(&prnt[3 * (size_t)i + 0]);
    float p1 = ld_pf(&prnt[3 * (size_t)i + 1]);
    float p2 = ld_pf(&prnt[3 * (size_t)i + 2]);
    float c0 = ld_pf(&child[3 * (size_t)i + 0]);
    float c1 = ld_pf(&child[3 * (size_t)i + 1]);
    float c2 = ld_pf(&child[3 * (size_t)i + 2]);

    float ep[9];
    const float* epp = eps + 9 * (size_t)i;
    #pragma unroll
    for (int k = 0; k < 9; k++) ep[k] = ld_pf(&epp[k]);

    const float* mu = &s_mu[9 * r];
    const float* sg = &s_sig[9 * r];

    // ---- M = mu + sigma*eps ; logits = M @ child ----
    float l0 = fmaf(fmaf(sg[0], ep[0], mu[0]), c0,
               fmaf(fmaf(sg[1], ep[1], mu[1]), c1,
                    fmaf(sg[2], ep[2], mu[2]) * c2));
    float l1 = fmaf(fmaf(sg[3], ep[3], mu[3]), c0,
               fmaf(fmaf(sg[4], ep[4], mu[4]), c1,
                    fmaf(sg[5], ep[5], mu[5]) * c2));
    float l2 = fmaf(fmaf(sg[6], ep[6], mu[6]), c0,
               fmaf(fmaf(sg[7], ep[7], mu[7]), c1,
                    fmaf(sg[8], ep[8], mu[8]) * c2));

    // ---- softmax ----
    float m  = fmaxf(l0, fmaxf(l1, l2));
    float e0 = __expf(l0 - m);
    float e1 = __expf(l1 - m);
    float e2 = __expf(l2 - m);
    float inv_es = __frcp_rn(e0 + e1 + e2);
    float cp0 = e0 * inv_es;
    float cp1 = e1 * inv_es;
    float cp2 = e2 * inv_es;

    // ---- masks (exact-zero semantics) ----
    float child_sum = c0 + c1 + c2;
    float prnt_sum  = p0 + p1 + p2;
    bool child_mask = (child_sum != 0.0f);
    bool copy_mask  = child_mask && (prnt_sum == 0.0f);
    bool alpha_mask = child_mask && (prnt_sum != 0.0f);

    // ---- scale ----
    float z0 = fmaxf(0.01f, p0 + cp0);
    float z1 = fmaxf(0.01f, p1 + cp1);
    float z2 = fmaxf(0.01f, p2 + cp2);
    float inv_zs = __frcp_rn(z0 + z1 + z2);
    z0 *= inv_zs; z1 *= inv_zs; z2 *= inv_zs;
    float entropy = -(z0 * __logf(z0) + z1 * __logf(z1) + z2 * __logf(z2));

    float dot  = p0 * cp0 + p1 * cp1 + p2 * cp2;
    float sqp  = p0 * p0 + p1 * p1 + p2 * p2;
    float sqc  = cp0 * cp0 + cp1 * cp1 + cp2 * cp2;
    float np   = (sqp == 0.0f) ? 0.0f : __fsqrt_rn(sqp);
    float nc   = (sqc == 0.0f) ? 0.0f : __fsqrt_rn(sqc);
    float norm = np * nc;
    norm = (norm == 0.0f) ? 1.0f : norm;
    float cosv = fmaxf(0.01f, dot * __frcp_rn(norm));
    float s = 42.0f * cosv * __frcp_rn(entropy);

    // ---- alpha ----
    float ob = 1.0f - b;
    float a0 = fmaf(ob, p0, b * cp0) * s;
    float a1 = fmaf(ob, p1, b * cp1) * s;
    float a2 = fmaf(ob, p2, b * cp2) * s;

    // ---- stores (plain: best DRAM% measured) ----
    size_t N = n;
    out[i] = copy_mask ? 1.0f : 0.0f;

    float* ocp = out + N + 3 * (size_t)i;
    ocp[0] = copy_mask ? cp0 : 0.0f;
    ocp[1] = copy_mask ? cp1 : 0.0f;
    ocp[2] = copy_mask ? cp2 : 0.0f;

    out[4 * N + i] = alpha_mask ? 1.0f : 0.0f;

    float* oal = out + 5 * N + 3 * (size_t)i;
    oal[0] = alpha_mask ? a0 : 0.0f;
    oal[1] = alpha_mask ? a1 : 0.0f;
    oal[2] = alpha_mask ? a2 : 0.0f;
}

extern "C" void kernel_launch(void* const* d_in, const int* in_sizes, int n_in,
                              void* d_out, int out_size) {
    const float* prnt   = (const float*)d_in[0];
    const float* child  = (const float*)d_in[1];
    const float* rel_mu = (const float*)d_in[2];
    const float* rel_sg = (const float*)d_in[3];
    const float* eps    = (const float*)d_in[4];
    const float* beta   = (const float*)d_in[5];
    const int*   rels   = (const int*)d_in[6];
    float* out = (float*)d_out;

    int n = in_sizes[5];  // beta element count == N
    int threads = 256;
    int blocks = (n + threads - 1) / threads;
    alpha_model_pf<<<blocks, threads>>>(prnt, child, rel_mu, rel_sg,
                                        eps, beta, rels, out, n);
}